// round 3
// baseline (speedup 1.0000x reference)
#include <cuda_runtime.h>
#include <cstdint>
#include <cstddef>

#define Bsz 16
#define H4 28
#define W4 64
#define HW (H4*W4)
#define C1 96
#define FEATC 631
#define FEATB (FEATC*HW)
#define FULL_H 448
#define FULL_W 1024

__device__ float gM[Bsz*9];
__device__ float gRfull[(size_t)Bsz*2*FULL_H*FULL_W];
__device__ float gRv[(size_t)Bsz*2*H4*FULL_W];
__device__ float gW1[(size_t)Bsz*C1*HW];
__device__ float gW2[(size_t)Bsz*C1*HW];

__device__ __forceinline__ unsigned long long pk2(float lo, float hi){
    unsigned long long r;
    asm("mov.b64 %0, {%1, %2};" : "=l"(r) : "f"(lo), "f"(hi));
    return r;
}
__device__ __forceinline__ void upk2(unsigned long long v, float& lo, float& hi){
    asm("mov.b64 {%0, %1}, %2;" : "=f"(lo), "=f"(hi) : "l"(v));
}
__device__ __forceinline__ unsigned long long ffma2(unsigned long long a,
                                                    unsigned long long b,
                                                    unsigned long long c){
    unsigned long long d;
    asm("fma.rn.f32x2 %0, %1, %2, %3;" : "=l"(d) : "l"(a), "l"(b), "l"(c));
    return d;
}
__device__ __forceinline__ float lrelu(float v){ return v >= 0.f ? v : 0.1f*v; }

// ---------------- K * R(q) * Kinv ----------------
__global__ void k_matrices(const float* __restrict__ quat,
                           const float* __restrict__ K,
                           const float* __restrict__ Kinv){
    int b = threadIdx.x;
    if (b >= Bsz) return;
    float q0=quat[b*4+0], q1=quat[b*4+1], q2=quat[b*4+2], q3=quat[b*4+3];
    float n = sqrtf(q0*q0+q1*q1+q2*q2+q3*q3);
    float w=q0/n, x=q1/n, y=q2/n, z=q3/n;
    float R[9];
    R[0]=1.f-2.f*(y*y+z*z); R[1]=2.f*(x*y-w*z);     R[2]=2.f*(x*z+w*y);
    R[3]=2.f*(x*y+w*z);     R[4]=1.f-2.f*(x*x+z*z); R[5]=2.f*(y*z-w*x);
    R[6]=2.f*(x*z-w*y);     R[7]=2.f*(y*z+w*x);     R[8]=1.f-2.f*(x*x+y*y);
    float T[9];
    for (int i=0;i<3;i++) for (int j=0;j<3;j++){
        float s=0.f;
        for (int k=0;k<3;k++) s += K[i*3+k]*R[k*3+j];
        T[i*3+j]=s;
    }
    for (int i=0;i<3;i++) for (int j=0;j<3;j++){
        float s=0.f;
        for (int k=0;k<3;k++) s += T[i*3+k]*Kinv[k*3+j];
        gM[b*9+i*3+j]=s;
    }
}

// ---------------- full-res rotation flow ----------------
__global__ void k_rfull(){
    long long idx = (long long)blockIdx.x*blockDim.x + threadIdx.x;
    const long long total = (long long)Bsz*FULL_H*FULL_W;
    if (idx >= total) return;
    int x = (int)(idx % FULL_W);
    int y = (int)((idx / FULL_W) % FULL_H);
    int b = (int)(idx / ((long long)FULL_W*FULL_H));
    const float* M = &gM[b*9];
    float fx = (float)x, fy = (float)y;
    float u = M[0]*fx + M[1]*fy + M[2];
    float v = M[3]*fx + M[4]*fy + M[5];
    float w = M[6]*fx + M[7]*fy + M[8];
    float rw = 1.0f / w;
    size_t o = ((size_t)(b*2)*FULL_H + y)*FULL_W + x;
    gRfull[o]                         = u*rw - fx;
    gRfull[o + (size_t)FULL_H*FULL_W] = v*rw - fy;
}

// ---------------- resize vertical 448 -> 28 ----------------
__global__ void k_resizeV(){
    int idx = blockIdx.x*blockDim.x + threadIdx.x;
    const int total = Bsz*H4*FULL_W;
    if (idx >= total) return;
    int x = idx % FULL_W;
    int i = (idx / FULL_W) % H4;
    int b = idx / (FULL_W*H4);
    float pos = 16.0f*i + 7.5f;
    int ys = 16*i - 8;
    float a0=0.f, a1=0.f, ws=0.f;
    const float* p0 = &gRfull[((size_t)(b*2)*FULL_H)*FULL_W + x];
    for (int t=0;t<32;t++){
        int yy = ys + t;
        if (yy < 0 || yy >= FULL_H) continue;
        float wgt = 1.0f - fabsf((float)yy - pos) * 0.0625f;
        a0 += wgt * p0[(size_t)yy*FULL_W];
        a1 += wgt * p0[((size_t)FULL_H + yy)*FULL_W];
        ws += wgt;
    }
    size_t o = ((size_t)(b*2)*H4 + i)*FULL_W + x;
    gRv[o]                     = a0/ws;
    gRv[o + (size_t)H4*FULL_W] = a1/ws;
}

// ---------------- resize horizontal 1024 -> 64, /16 -> feat[529,530] -------
__global__ void k_resizeH(float* __restrict__ feat){
    int idx = blockIdx.x*blockDim.x + threadIdx.x;
    const int total = Bsz*HW;
    if (idx >= total) return;
    int j = idx % W4;
    int i = (idx / W4) % H4;
    int b = idx / HW;
    float pos = 16.0f*j + 7.5f;
    int xs = 16*j - 8;
    float a0=0.f, a1=0.f, ws=0.f;
    const float* p0 = &gRv[((size_t)(b*2)*H4 + i)*FULL_W];
    const float* p1 = p0 + (size_t)H4*FULL_W;
    for (int t=0;t<32;t++){
        int xx = xs + t;
        if (xx < 0 || xx >= FULL_W) continue;
        float wgt = 1.0f - fabsf((float)xx - pos) * 0.0625f;
        a0 += wgt * p0[xx];
        a1 += wgt * p1[xx];
        ws += wgt;
    }
    size_t o = (size_t)b*FEATB + (size_t)529*HW + i*W4 + j;
    feat[o]      = (a0/ws)*0.0625f;
    feat[o + HW] = (a1/ws)*0.0625f;
}

// ---------------- copy tenOne -> feat[531..626] ----------------
__global__ void k_copyone(const float* __restrict__ one, float* __restrict__ feat){
    int idx = blockIdx.x*blockDim.x + threadIdx.x;
    const int total = Bsz*C1*HW;
    if (idx >= total) return;
    int p = idx % HW;
    int c = (idx / HW) % C1;
    int b = idx / (HW*C1);
    feat[(size_t)b*FEATB + (size_t)(531+c)*HW + p] = one[idx];
}

// ---------------- deconv4s2 prev_flow -> feat[627,628] ----------------
__global__ void k_deconv_flow(const float* __restrict__ pf,
                              const float* __restrict__ w,
                              const float* __restrict__ bias,
                              float* __restrict__ feat){
    int idx = blockIdx.x*blockDim.x + threadIdx.x;
    const int total = Bsz*2*HW;
    if (idx >= total) return;
    int x = idx % W4;
    int y = (idx / W4) % H4;
    int o = (idx / HW) % 2;
    int b = idx / (2*HW);
    float acc = bias[o];
    for (int t=0;t<2;t++){
        int ky = (y & 1) + 2*t;
        int iy = (y + ky - 2) / 2;
        if ((y + ky - 2) < 0 || iy >= 14) continue;
        for (int s=0;s<2;s++){
            int kx = (x & 1) + 2*s;
            int ix = (x + kx - 2) / 2;
            if ((x + kx - 2) < 0 || ix >= 32) continue;
            for (int c=0;c<2;c++){
                acc += pf[((b*2 + c)*14 + iy)*32 + ix]
                     * w[((c*2 + o)*4 + (3-ky))*4 + (3-kx)];
            }
        }
    }
    feat[(size_t)b*FEATB + (size_t)(627+o)*HW + y*W4 + x] = acc;
}

// ---------------- deconv4s2 prev_feat (663 -> 2) -> feat[629,630] ----------
__global__ void k_deconv_feat(const float* __restrict__ pf,
                              const float* __restrict__ w,
                              const float* __restrict__ bias,
                              float* __restrict__ feat){
    int idx = blockIdx.x*blockDim.x + threadIdx.x;
    const int total = Bsz*HW;
    if (idx >= total) return;
    int x = idx % W4;
    int y = (idx / W4) % H4;
    int b = idx / HW;

    int iys[2], was[2], nky=0;
    for (int t=0;t<2;t++){
        int ky = (y & 1) + 2*t;
        int num = y + ky - 2;
        int iy = num / 2;
        if (num >= 0 && iy < 14){ iys[nky] = iy; was[nky] = 3-ky; nky++; }
    }
    int ixs[2], wbs[2], nkx=0;
    for (int t=0;t<2;t++){
        int kx = (x & 1) + 2*t;
        int num = x + kx - 2;
        int ix = num / 2;
        if (num >= 0 && ix < 32){ ixs[nkx] = ix; wbs[nkx] = 3-kx; nkx++; }
    }
    float a0 = bias[0], a1 = bias[1];
    const float* pb = pf + (size_t)b*663*14*32;
    for (int c=0;c<663;c++){
        const float* base = pb + (size_t)c*14*32;
        const float* wb   = w + (size_t)c*32;
        for (int ti=0; ti<nky; ti++){
            for (int tj=0; tj<nkx; tj++){
                float v = base[iys[ti]*32 + ixs[tj]];
                int wo = was[ti]*4 + wbs[tj];
                a0 += v * wb[wo];
                a1 += v * wb[16 + wo];
            }
        }
    }
    size_t o = (size_t)b*FEATB + (size_t)629*HW + y*W4 + x;
    feat[o]      = a0;
    feat[o + HW] = a1;
}

// ---------------- bilinear warp ----------------
__device__ __forceinline__ void warp_px(const float* __restrict__ srcB,
                                        float* __restrict__ dstB,
                                        float fx, float fy, int x, int y){
    float xx = (float)x + fx, yy = (float)y + fy;
    float x0 = floorf(xx), y0 = floorf(yy);
    float wx = xx - x0, wy = yy - y0;
    float ys2[2] = { y0, y0 + 1.f };
    float xs2[2] = { x0, x0 + 1.f };
    float wyv[2] = { 1.f - wy, wy };
    float wxv[2] = { 1.f - wx, wx };
    float wgt[4]; int off[4];
    #pragma unroll
    for (int i=0;i<2;i++){
        #pragma unroll
        for (int j=0;j<2;j++){
            bool valid = (ys2[i] >= 0.f) && (ys2[i] <= (float)(H4-1))
                      && (xs2[j] >= 0.f) && (xs2[j] <= (float)(W4-1));
            float yc = fminf(fmaxf(ys2[i], 0.f), (float)(H4-1));
            float xc = fminf(fmaxf(xs2[j], 0.f), (float)(W4-1));
            off[i*2+j] = (int)yc * W4 + (int)xc;
            wgt[i*2+j] = valid ? (wyv[i]*wxv[j]) : 0.f;
        }
    }
    int obase = y*W4 + x;
    #pragma unroll 4
    for (int c=0;c<C1;c++){
        const float* s = srcB + (size_t)c*HW;
        dstB[(size_t)c*HW + obase] =
            wgt[0]*s[off[0]] + wgt[1]*s[off[1]] + wgt[2]*s[off[2]] + wgt[3]*s[off[3]];
    }
}

__global__ void k_warp1(const float* __restrict__ tenTwo, const float* __restrict__ feat){
    int idx = blockIdx.x*blockDim.x + threadIdx.x;
    if (idx >= Bsz*HW) return;
    int x = idx % W4, y = (idx / W4) % H4, b = idx / HW;
    const float* fp = feat + (size_t)b*FEATB + (size_t)529*HW + y*W4 + x;
    warp_px(tenTwo + (size_t)b*C1*HW, gW1 + (size_t)b*C1*HW, fp[0], fp[HW], x, y);
}
__global__ void k_warp2(const float* __restrict__ feat){
    int idx = blockIdx.x*blockDim.x + threadIdx.x;
    if (idx >= Bsz*HW) return;
    int x = idx % W4, y = (idx / W4) % H4, b = idx / HW;
    const float* fp = feat + (size_t)b*FEATB + (size_t)627*HW + y*W4 + x;
    warp_px(gW1 + (size_t)b*C1*HW, gW2 + (size_t)b*C1*HW,
            fp[0]*1.25f, fp[HW]*1.25f, x, y);
}

// ---------------- correlation (81ch) + lrelu -> feat[448..528] -------------
__global__ void __launch_bounds__(256) k_corr(const float* __restrict__ one,
                                              float* __restrict__ feat){
    __shared__ float s1[8][4][64];
    __shared__ float s2[8][12][72];
    int tid = threadIdx.x;
    int tx = tid % 64, tyl = tid / 64;
    int b = blockIdx.y, rt = blockIdx.x;
    int y = rt*4 + tyl;
    float acc[81];
    #pragma unroll
    for (int d=0; d<81; d++) acc[d] = 0.f;
    const float* oneB = one + (size_t)b*C1*HW;
    const float* twoB = gW2 + (size_t)b*C1*HW;

    for (int c0=0; c0<C1; c0+=8){
        __syncthreads();
        for (int i=tid; i<8*4*64; i+=256){
            int c = i / 256; int r = (i / 64) % 4; int xx = i % 64;
            s1[c][r][xx] = oneB[(size_t)(c0+c)*HW + (rt*4+r)*64 + xx];
        }
        for (int i=tid; i<8*12*72; i+=256){
            int c = i / (12*72); int rem = i % (12*72);
            int r = rem / 72; int xx = rem % 72;
            int gy = rt*4 + r - 4, gx = xx - 4;
            float v = 0.f;
            if (gy >= 0 && gy < H4 && gx >= 0 && gx < W4)
                v = twoB[(size_t)(c0+c)*HW + gy*64 + gx];
            s2[c][r][xx] = v;
        }
        __syncthreads();
        #pragma unroll
        for (int c=0;c<8;c++){
            float f1 = s1[c][tyl][tx];
            #pragma unroll
            for (int dy=0;dy<9;dy++){
                const float* row = &s2[c][tyl+dy][tx];
                #pragma unroll
                for (int dx=0;dx<9;dx++)
                    acc[dy*9+dx] += f1 * row[dx];
            }
        }
    }
    float* fb = feat + (size_t)b*FEATB + (size_t)448*HW + y*64 + tx;
    const float inv = 1.0f/96.0f;
    #pragma unroll
    for (int d=0; d<81; d++)
        fb[(size_t)d*HW] = lrelu(acc[d]*inv);
}

// ---------------- dense 3x3 conv + lrelu (packed f32x2) --------------------
template<int NPAIR>
__global__ void __launch_bounds__(256) k_conv(
    const float* __restrict__ inb,
    const float* __restrict__ W,
    const float* __restrict__ Bv,
    float* __restrict__ outb,
    int cin, long long ostride)
{
    const int b  = blockIdx.x >> 2;
    const int rt = blockIdx.x & 3;
    const int og = blockIdx.y * (2*NPAIR);
    const int tid = threadIdx.x;
    const int x  = tid & 63;
    const int yl = tid >> 6;
    const int y0 = rt*8;

    __shared__ float sin_[4][10][72];
    __shared__ unsigned long long sw[4][9][NPAIR];

    const float* ibase = inb + (size_t)b*FEATB;

    unsigned long long acc0[NPAIR], acc1[NPAIR];
    #pragma unroll
    for (int p=0;p<NPAIR;p++){
        unsigned long long bb = pk2(Bv[og+2*p], Bv[og+2*p+1]);
        acc0[p]=bb; acc1[p]=bb;
    }

    for (int c0=0; c0<cin; c0+=4){
        __syncthreads();
        for (int i=tid; i<4*10*66; i+=256){
            int cc = i/660; int r = (i/66)%10; int col = i%66;
            int gy = y0 + r - 1; int gx = col - 1;
            int c = c0 + cc;
            float v = 0.f;
            if (c < cin && gy>=0 && gy<H4 && gx>=0 && gx<W4)
                v = ibase[(size_t)c*HW + gy*W4 + gx];
            sin_[cc][r][col] = v;
        }
        for (int i=tid; i<4*9*NPAIR; i+=256){
            int cc = i/(9*NPAIR); int k = (i/NPAIR)%9; int p = i%NPAIR;
            int c = c0+cc;
            float w0=0.f, w1=0.f;
            if (c < cin){
                w0 = W[((size_t)(og+2*p  )*cin + c)*9 + k];
                w1 = W[((size_t)(og+2*p+1)*cin + c)*9 + k];
            }
            sw[cc][k][p] = pk2(w0,w1);
        }
        __syncthreads();
        #pragma unroll
        for (int cc=0; cc<4; cc++){
            float i0[9], i1[9];
            #pragma unroll
            for (int dy=0;dy<3;dy++)
                #pragma unroll
                for (int dx=0;dx<3;dx++){
                    i0[dy*3+dx] = sin_[cc][yl+dy][x+dx];
                    i1[dy*3+dx] = sin_[cc][yl+4+dy][x+dx];
                }
            #pragma unroll
            for (int k=0;k<9;k++){
                unsigned long long v0 = pk2(i0[k], i0[k]);
                unsigned long long v1 = pk2(i1[k], i1[k]);
                #pragma unroll
                for (int p=0;p<NPAIR;p++){
                    unsigned long long wv = sw[cc][k][p];
                    acc0[p] = ffma2(v0, wv, acc0[p]);
                    acc1[p] = ffma2(v1, wv, acc1[p]);
                }
            }
        }
    }
    int y_a = y0 + yl, y_b = y0 + yl + 4;
    float* obase = outb + (size_t)b*ostride;
    #pragma unroll
    for (int p=0;p<NPAIR;p++){
        float a,bb; upk2(acc0[p], a, bb);
        if (y_a < H4){
            obase[(size_t)(og+2*p  )*HW + y_a*W4 + x] = lrelu(a);
            obase[(size_t)(og+2*p+1)*HW + y_a*W4 + x] = lrelu(bb);
        }
        upk2(acc1[p], a, bb);
        if (y_b < H4){
            obase[(size_t)(og+2*p  )*HW + y_b*W4 + x] = lrelu(a);
            obase[(size_t)(og+2*p+1)*HW + y_b*W4 + x] = lrelu(bb);
        }
    }
}

extern "C" void kernel_launch(void* const* d_in, const int* in_sizes, int n_in,
                              void* d_out, int out_size) {
    const float* tenOne   = (const float*)d_in[0];
    const float* tenTwo   = (const float*)d_in[1];
    const float* prev_flow= (const float*)d_in[2];
    const float* prev_feat= (const float*)d_in[3];
    const float* quat     = (const float*)d_in[4];
    const float* K        = (const float*)d_in[5];
    const float* Kinv     = (const float*)d_in[6];
    const float* upflow_w = (const float*)d_in[7];
    const float* upflow_b = (const float*)d_in[8];
    const float* upfeat_w = (const float*)d_in[9];
    const float* upfeat_b = (const float*)d_in[10];
    const float* w1=(const float*)d_in[11]; const float* b1=(const float*)d_in[12];
    const float* w2=(const float*)d_in[13]; const float* b2=(const float*)d_in[14];
    const float* w3=(const float*)d_in[15]; const float* b3=(const float*)d_in[16];
    const float* w4=(const float*)d_in[17]; const float* b4=(const float*)d_in[18];
    const float* w5=(const float*)d_in[19]; const float* b5=(const float*)d_in[20];
    const float* w6=(const float*)d_in[21]; const float* b6=(const float*)d_in[22];

    float* out      = (float*)d_out;
    float* flow_out = out;                       // (B,2,28,64)
    float* feat     = out + (size_t)Bsz*2*HW;    // (B,631,28,64)

    k_matrices<<<1,32>>>(quat, K, Kinv);
    k_rfull<<<(Bsz*FULL_H*FULL_W)/256, 256>>>();
    k_resizeV<<<(Bsz*H4*FULL_W)/256, 256>>>();
    k_resizeH<<<(Bsz*HW+255)/256, 256>>>(feat);
    k_copyone<<<(Bsz*C1*HW)/256, 256>>>(tenOne, feat);
    k_deconv_flow<<<(Bsz*2*HW)/256, 256>>>(prev_flow, upflow_w, upflow_b, feat);
    k_deconv_feat<<<(Bsz*HW)/256, 256>>>(prev_feat, upfeat_w, upfeat_b, feat);
    k_warp1<<<(Bsz*HW)/256, 256>>>(tenTwo, feat);
    k_warp2<<<(Bsz*HW)/256, 256>>>(feat);
    k_corr<<<dim3(7, Bsz), 256>>>(tenOne, feat);

    // dense conv tower: read [cs,631), write [cs-cout, cs)
    k_conv<8><<<dim3(Bsz*4, 8), 256>>>(feat + (size_t)448*HW, w1, b1,
                                       feat + (size_t)320*HW, 183, FEATB);
    k_conv<8><<<dim3(Bsz*4, 8), 256>>>(feat + (size_t)320*HW, w2, b2,
                                       feat + (size_t)192*HW, 311, FEATB);
    k_conv<8><<<dim3(Bsz*4, 6), 256>>>(feat + (size_t)192*HW, w3, b3,
                                       feat + (size_t) 96*HW, 439, FEATB);
    k_conv<8><<<dim3(Bsz*4, 4), 256>>>(feat + (size_t) 96*HW, w4, b4,
                                       feat + (size_t) 32*HW, 535, FEATB);
    k_conv<8><<<dim3(Bsz*4, 2), 256>>>(feat + (size_t) 32*HW, w5, b5,
                                       feat,                   599, FEATB);
    k_conv<1><<<dim3(Bsz*4, 1), 256>>>(feat,                   w6, b6,
                                       flow_out,               631, 2*HW);
}